// round 13
// baseline (speedup 1.0000x reference)
#include <cuda_runtime.h>
#include <cuda_bf16.h>
#include <cuda_fp16.h>

// Problem constants
#define BB   512
#define SS   1024
#define SSP  (SS + 2)  // padded rows per batch (prefetch overrun)
#define FIN  16        // features per (b,s); feature 15 is delta
#define HH   64
#define GG   192       // 3*H
#define NBC  2         // batches per scan CTA (shared weights, kh <-> batch)
#define NT   128       // 4 warps, one sync domain
#define XROWS 128      // rows per x-projection block
#define NTP  384       // x-projection block threads (4 row-groups x 96 g-pairs)

typedef unsigned long long u64;

// Device scratch (sanctioned alternative to cudaMalloc)
__device__ __half g_xp[(size_t)BB * SSP * GG];   // x-projection + folded biases (fp16, ~202 MB)

// ---- packed f32x2 helpers (bit-exact fp32, 2 FMA per fma-pipe slot) ----
__device__ __forceinline__ u64 pack2(float lo, float hi) {
    u64 r; asm("mov.b64 %0, {%1, %2};" : "=l"(r) : "f"(lo), "f"(hi)); return r;
}
__device__ __forceinline__ void unpack2(u64 v, float& lo, float& hi) {
    asm("mov.b64 {%0, %1}, %2;" : "=f"(lo), "=f"(hi) : "l"(v));
}
__device__ __forceinline__ u64 fma2(u64 a, u64 b, u64 c) {
    u64 d; asm("fma.rn.f32x2 %0, %1, %2, %3;" : "=l"(d) : "l"(a), "l"(b), "l"(c)); return d;
}
__device__ __forceinline__ u64 add2(u64 a, u64 b) {
    u64 d; asm("add.rn.f32x2 %0, %1, %2;" : "=l"(d) : "l"(a), "l"(b)); return d;
}
__device__ __forceinline__ float tanh_fast(float x) {
    float t; asm("tanh.approx.f32 %0, %1;" : "=f"(t) : "f"(x)); return t;
}

// ---------------- Kernel 1: x-projection pre-pass (fp16 out, biases folded) ----------------
// Thread = (row-group, g-pair). Stores half2 (4B) coalesced.
// For g<128 (z,r gates): xp = x.K + b_in[g] + b_rec[g]
// For g>=128 (h gate):   xp = x.K + b_in[g]
__global__ __launch_bounds__(NTP)
void xproj_kernel(const float* __restrict__ inputs,
                  const float* __restrict__ k_in,
                  const float* __restrict__ bias) {
    __shared__ __align__(16) float sx[XROWS * FIN];    // 8 KB
    const int gp  = threadIdx.x % 96;                  // g-pair: columns 2gp, 2gp+1
    const int grp = threadIdx.x / 96;                  // row group 0..3
    const int g0  = 2 * gp, g1 = 2 * gp + 1;
    const int bb  = blockIdx.x / (SS / XROWS);
    const int s0  = (blockIdx.x % (SS / XROWS)) * XROWS;
    const size_t row0  = (size_t)bb * SS + s0;
    const size_t drow0 = (size_t)bb * SSP + s0;

    u64 KA[8], KB[8];
    #pragma unroll
    for (int f2 = 0; f2 < 8; f2++) {
        float a_lo = k_in[(2 * f2) * GG + g0];
        float a_hi = (2 * f2 + 1 < 15) ? k_in[(2 * f2 + 1) * GG + g0] : 0.0f;
        float b_lo = k_in[(2 * f2) * GG + g1];
        float b_hi = (2 * f2 + 1 < 15) ? k_in[(2 * f2 + 1) * GG + g1] : 0.0f;
        KA[f2] = pack2(a_lo, a_hi);
        KB[f2] = pack2(b_lo, b_hi);
    }
    const float bf0 = bias[g0] + ((g0 < 128) ? bias[GG + g0] : 0.0f);
    const float bf1 = bias[g1] + ((g1 < 128) ? bias[GG + g1] : 0.0f);

    const float4* src = (const float4*)(inputs + row0 * FIN);
    for (int i = threadIdx.x; i < XROWS * 4; i += NTP) ((float4*)sx)[i] = src[i];
    __syncthreads();

    __half2* dst2 = (__half2*)(g_xp + drow0 * GG);
    #pragma unroll 4
    for (int rr = 0; rr < XROWS / 4; rr++) {
        const int r = grp * (XROWS / 4) + rr;
        const ulonglong2* xr = (const ulonglong2*)(sx + r * FIN);
        ulonglong2 xv0 = xr[0], xv1 = xr[1], xv2 = xr[2], xv3 = xr[3];
        u64 a0 = fma2(xv0.x, KA[0], 0ull);
        u64 b0 = fma2(xv0.x, KB[0], 0ull);
        u64 a1 = fma2(xv0.y, KA[1], 0ull);
        u64 b1 = fma2(xv0.y, KB[1], 0ull);
        a0 = fma2(xv1.x, KA[2], a0);  b0 = fma2(xv1.x, KB[2], b0);
        a1 = fma2(xv1.y, KA[3], a1);  b1 = fma2(xv1.y, KB[3], b1);
        a0 = fma2(xv2.x, KA[4], a0);  b0 = fma2(xv2.x, KB[4], b0);
        a1 = fma2(xv2.y, KA[5], a1);  b1 = fma2(xv2.y, KB[5], b1);
        a0 = fma2(xv3.x, KA[6], a0);  b0 = fma2(xv3.x, KB[6], b0);
        a1 = fma2(xv3.y, KA[7], a1);  b1 = fma2(xv3.y, KB[7], b1);
        float lo, hi;
        unpack2(add2(a0, a1), lo, hi); const float v0 = bf0 + (lo + hi);
        unpack2(add2(b0, b1), lo, hi); const float v1 = bf1 + (lo + hi);
        dst2[(size_t)r * 96 + gp] = __floats2half2_rn(v0, v1);
    }
}

// ---------------- Kernel 2: GRU scan — 2 batches/CTA sharing weights ----------------
// Thread = (jj, kh): jj = owned column triple, kh = k-half AND finalized batch.
// Each thread computes k-half partials for BOTH batches with the same 48 weight regs,
// exchanges the other batch's partial via one shfl.xor(16), and runs the gate chain
// for exactly one batch. One __syncthreads per step; 2 CTAs/SM -> 4 batches/SM.
__global__ __launch_bounds__(NT, 2)
void gru_scan_kernel(const float* __restrict__ inputs,   // (B,S,16) - for delta mean
                     const float* __restrict__ r_in,     // (64,192)
                     const float* __restrict__ bias,     // (2,192)
                     const float* __restrict__ w1,       // (64,64)
                     const float* __restrict__ b1,       // (64)
                     const float* __restrict__ bn_gamma,
                     const float* __restrict__ bn_beta,
                     const float* __restrict__ bn_mean,
                     const float* __restrict__ bn_var,
                     const float* __restrict__ w2,       // (64,1)
                     const float* __restrict__ b2,       // (1)
                     const float* __restrict__ Tp,       // (1)
                     float* __restrict__ out)            // (B,1)
{
    __shared__ __align__(16) float sm_h[2][NBC][HH];   // double-buffered hidden state per batch
    __shared__ float sm_e[NBC][HH];
    __shared__ float sm_r[NBC][HH];

    const int tid  = threadIdx.x;
    const int lane = tid & 31;
    const int w4   = tid >> 5;               // warp 0..3
    const int jj   = w4 * 16 + (lane & 15);  // owned column triple 0..63
    const int kh   = lane >> 4;              // k-half AND batch this thread finalizes

    // Recurrent weights for columns jj (z), 64+jj (r), 128+jj (h), k-half only
    u64 Rz[16], Rr[16], Rh[16];
    #pragma unroll
    for (int t2 = 0; t2 < 16; t2++) {
        const int k = 32 * kh + 2 * t2;
        Rz[t2] = pack2(r_in[k * GG + jj],        r_in[(k + 1) * GG + jj]);
        Rr[t2] = pack2(r_in[k * GG + 64 + jj],   r_in[(k + 1) * GG + 64 + jj]);
        Rh[t2] = pack2(r_in[k * GG + 128 + jj],  r_in[(k + 1) * GG + 128 + jj]);
    }
    const float brh = bias[GG + 128 + jj];   // only h-gate recurrent bias remains

    if (tid < NBC * HH) ((float*)sm_h[0])[tid] = 0.0f;

    // This thread's finalized batch and its xp stream
    const int bmine = blockIdx.x * NBC + kh;
    const __half* xpp = g_xp + (size_t)bmine * SSP * GG;
    float xz0 = __half2float(xpp[jj]);
    float xr0 = __half2float(xpp[64 + jj]);
    float xh0 = __half2float(xpp[128 + jj]);
    float xz1 = __half2float(xpp[GG + jj]);
    float xr1 = __half2float(xpp[GG + 64 + jj]);
    float xh1 = __half2float(xpp[GG + 128 + jj]);
    __syncthreads();

    for (int s = 0; s < SS; s++) {
        const int p = s & 1;

        // prefetch s+2 for my batch (padded rows: no predicate)
        const __half* qp = xpp + (size_t)(s + 2) * GG;
        float xz2 = __half2float(qp[jj]);
        float xr2 = __half2float(qp[64 + jj]);
        float xh2 = __half2float(qp[128 + jj]);

        // k-half partial dots for MY batch (kh) and the OTHER batch (kh^1),
        // same weight registers, 96 fma2 total, 12 parallel chains of depth 8.
        const ulonglong2* hm = (const ulonglong2*)(&sm_h[p][kh][32 * kh]);
        const ulonglong2* ho4 = (const ulonglong2*)(&sm_h[p][kh ^ 1][32 * kh]);
        u64 mz0 = 0ull, mz1 = 0ull, mr0 = 0ull, mr1 = 0ull, mh0 = 0ull, mh1 = 0ull;
        u64 oz0 = 0ull, oz1 = 0ull, or0 = 0ull, or1 = 0ull, oh0 = 0ull, oh1 = 0ull;
        #pragma unroll
        for (int q2 = 0; q2 < 8; q2++) {
            ulonglong2 hv = hm[q2];
            ulonglong2 gv = ho4[q2];
            mz0 = fma2(hv.x, Rz[2 * q2],     mz0);
            mr0 = fma2(hv.x, Rr[2 * q2],     mr0);
            mh0 = fma2(hv.x, Rh[2 * q2],     mh0);
            mz1 = fma2(hv.y, Rz[2 * q2 + 1], mz1);
            mr1 = fma2(hv.y, Rr[2 * q2 + 1], mr1);
            mh1 = fma2(hv.y, Rh[2 * q2 + 1], mh1);
            oz0 = fma2(gv.x, Rz[2 * q2],     oz0);
            or0 = fma2(gv.x, Rr[2 * q2],     or0);
            oh0 = fma2(gv.x, Rh[2 * q2],     oh0);
            oz1 = fma2(gv.y, Rz[2 * q2 + 1], oz1);
            or1 = fma2(gv.y, Rr[2 * q2 + 1], or1);
            oh1 = fma2(gv.y, Rh[2 * q2 + 1], oh1);
        }
        float lo, hi;
        unpack2(add2(mz0, mz1), lo, hi);  const float pzm = lo + hi;
        unpack2(add2(mr0, mr1), lo, hi);  const float prm = lo + hi;
        unpack2(add2(mh0, mh1), lo, hi);  const float phm = lo + hi;
        unpack2(add2(oz0, oz1), lo, hi);  const float pzo = lo + hi;
        unpack2(add2(or0, or1), lo, hi);  const float pro = lo + hi;
        unpack2(add2(oh0, oh1), lo, hi);  const float pho = lo + hi;

        // exchange: partner (lane^16) holds the complementary k-half of MY batch.
        // I send my partial of HIS batch; I receive his partial of MINE.
        const float sz = pzm + __shfl_xor_sync(0xffffffffu, pzo, 16);
        const float sr = prm + __shfl_xor_sync(0xffffffffu, pro, 16);
        const float sh = phm + __shfl_xor_sync(0xffffffffu, pho, 16);

        // gate chain for my batch only (MUFU.TANH; sigmoid(x)=0.5+0.5*tanh(x/2))
        const float z  = 0.5f + 0.5f * tanh_fast(0.5f * (xz0 + sz));
        const float r  = 0.5f + 0.5f * tanh_fast(0.5f * (xr0 + sr));
        const float hh = tanh_fast(xh0 + r * (brh + sh));
        const float hold = sm_h[p][kh][jj];
        sm_h[p ^ 1][kh][jj] = z * (hold - hh) + hh;

        xz0 = xz1; xr0 = xr1; xh0 = xh1;
        xz1 = xz2; xr1 = xr2; xh1 = xh2;
        __syncthreads();
    }

    // ---------- delta mean (threads 0-63 -> batch 0, 64-127 -> batch 1) ----------
    const int u  = tid >> 6;            // epilogue batch slot
    const int j6 = tid & 63;
    const int b  = blockIdx.x * NBC + u;
    {
        float sacc = 0.0f;
        const float* dp = inputs + ((size_t)b * SS + (size_t)j6 * 16) * FIN + 15;
        #pragma unroll
        for (int i = 0; i < 16; i++) sacc += dp[(size_t)i * FIN];
        sm_r[u][j6] = sacc;
    }
    __syncthreads();
    if (j6 < 16) sm_r[u][j6] += sm_r[u][j6 + 16] + sm_r[u][j6 + 32] + sm_r[u][j6 + 48];
    __syncthreads();
    if (j6 < 4)  sm_r[u][j6] += sm_r[u][j6 + 4] + sm_r[u][j6 + 8] + sm_r[u][j6 + 12];
    __syncthreads();
    const float db = Tp[0] * ((sm_r[u][0] + sm_r[u][1]) + (sm_r[u][2] + sm_r[u][3])) * (1.0f / (float)SS);

    // ---------- Epilogue: MLP head + BN (final h in buffer 0; SS even) ----------
    const float* hf = sm_h[0][u];
    {
        float acc = b1[j6];
        #pragma unroll 8
        for (int k = 0; k < HH; k++)
            acc += (hf[k] + db) * w1[k * HH + j6];
        float hr = fmaxf(acc, 0.0f);
        float hb = (hr - bn_mean[j6]) * rsqrtf(bn_var[j6] + 1e-3f) * bn_gamma[j6] + bn_beta[j6];
        sm_e[u][j6] = hb * w2[j6];
    }
    __syncthreads();

    if (j6 == 0) {
        float acc = b2[0];
        #pragma unroll 8
        for (int k = 0; k < HH; k++) acc += sm_e[u][k];
        out[b] = acc;
    }
}

extern "C" void kernel_launch(void* const* d_in, const int* in_sizes, int n_in,
                              void* d_out, int out_size) {
    const float* inputs   = (const float*)d_in[0];
    const float* gk       = (const float*)d_in[1];
    const float* grk      = (const float*)d_in[2];
    const float* gbias    = (const float*)d_in[3];
    const float* w1       = (const float*)d_in[4];
    const float* b1       = (const float*)d_in[5];
    const float* bn_gamma = (const float*)d_in[6];
    const float* bn_beta  = (const float*)d_in[7];
    const float* bn_mean  = (const float*)d_in[8];
    const float* bn_var   = (const float*)d_in[9];
    const float* w2       = (const float*)d_in[10];
    const float* b2       = (const float*)d_in[11];
    const float* T        = (const float*)d_in[12];
    float* out = (float*)d_out;

    xproj_kernel<<<(BB * SS) / XROWS, NTP>>>(inputs, gk, gbias);
    gru_scan_kernel<<<BB / NBC, NT>>>(inputs, grk, gbias, w1, b1,
                                      bn_gamma, bn_beta, bn_mean, bn_var,
                                      w2, b2, T, out);
}

// round 14
// speedup vs baseline: 1.4525x; 1.4525x over previous
#include <cuda_runtime.h>
#include <cuda_bf16.h>
#include <cuda_fp16.h>

// Problem constants
#define BB   512
#define SS   1024
#define SSP  (SS + 2)  // padded rows per batch (prefetch overrun; pad rows stay 0)
#define FIN  16        // features per (b,s); feature 15 is delta
#define HH   64
#define GG   192       // 3*H
#define XROWS 128      // rows per x-projection block
#define NTP  384       // x-projection block threads (4 row-groups x 96 g-pairs)

typedef unsigned long long u64;

// Device scratch (sanctioned alternative to cudaMalloc)
__device__ __half g_xp[(size_t)BB * SSP * GG];   // x-projection + folded biases (fp16, ~202 MB)

// ---- packed f32x2 helpers (bit-exact fp32, 2 FMA per fma-pipe slot) ----
__device__ __forceinline__ u64 pack2(float lo, float hi) {
    u64 r; asm("mov.b64 %0, {%1, %2};" : "=l"(r) : "f"(lo), "f"(hi)); return r;
}
__device__ __forceinline__ void unpack2(u64 v, float& lo, float& hi) {
    asm("mov.b64 {%0, %1}, %2;" : "=f"(lo), "=f"(hi) : "l"(v));
}
__device__ __forceinline__ u64 fma2(u64 a, u64 b, u64 c) {
    u64 d; asm("fma.rn.f32x2 %0, %1, %2, %3;" : "=l"(d) : "l"(a), "l"(b), "l"(c)); return d;
}
__device__ __forceinline__ u64 add2(u64 a, u64 b) {
    u64 d; asm("add.rn.f32x2 %0, %1, %2;" : "=l"(d) : "l"(a), "l"(b)); return d;
}
__device__ __forceinline__ float tanh_fast(float x) {
    float t; asm("tanh.approx.f32 %0, %1;" : "=f"(t) : "f"(x)); return t;
}

// ---------------- Kernel 1: x-projection pre-pass (fp16 out, biases folded) ----------------
// Thread = (row-group, g-pair). Stores half2 (4B) coalesced: 96 consecutive half2 per row.
// For g<128 (z,r gates): xp = x.K + b_in[g] + b_rec[g]
// For g>=128 (h gate):   xp = x.K + b_in[g]
__global__ __launch_bounds__(NTP)
void xproj_kernel(const float* __restrict__ inputs,
                  const float* __restrict__ k_in,
                  const float* __restrict__ bias) {
    __shared__ __align__(16) float sx[XROWS * FIN];    // 8 KB
    const int gp  = threadIdx.x % 96;                  // g-pair: columns 2gp, 2gp+1
    const int grp = threadIdx.x / 96;                  // row group 0..3
    const int g0  = 2 * gp, g1 = 2 * gp + 1;
    const int bb  = blockIdx.x / (SS / XROWS);
    const int s0  = (blockIdx.x % (SS / XROWS)) * XROWS;
    const size_t row0  = (size_t)bb * SS + s0;
    const size_t drow0 = (size_t)bb * SSP + s0;

    u64 KA[8], KB[8];
    #pragma unroll
    for (int f2 = 0; f2 < 8; f2++) {
        float a_lo = k_in[(2 * f2) * GG + g0];
        float a_hi = (2 * f2 + 1 < 15) ? k_in[(2 * f2 + 1) * GG + g0] : 0.0f;
        float b_lo = k_in[(2 * f2) * GG + g1];
        float b_hi = (2 * f2 + 1 < 15) ? k_in[(2 * f2 + 1) * GG + g1] : 0.0f;
        KA[f2] = pack2(a_lo, a_hi);
        KB[f2] = pack2(b_lo, b_hi);
    }
    const float bf0 = bias[g0] + ((g0 < 128) ? bias[GG + g0] : 0.0f);
    const float bf1 = bias[g1] + ((g1 < 128) ? bias[GG + g1] : 0.0f);

    const float4* src = (const float4*)(inputs + row0 * FIN);
    for (int i = threadIdx.x; i < XROWS * 4; i += NTP) ((float4*)sx)[i] = src[i];
    __syncthreads();

    __half2* dst2 = (__half2*)(g_xp + drow0 * GG);
    #pragma unroll 4
    for (int rr = 0; rr < XROWS / 4; rr++) {
        const int r = grp * (XROWS / 4) + rr;
        const ulonglong2* xr = (const ulonglong2*)(sx + r * FIN);
        ulonglong2 xv0 = xr[0], xv1 = xr[1], xv2 = xr[2], xv3 = xr[3];
        u64 a0 = fma2(xv0.x, KA[0], 0ull);
        u64 b0 = fma2(xv0.x, KB[0], 0ull);
        u64 a1 = fma2(xv0.y, KA[1], 0ull);
        u64 b1 = fma2(xv0.y, KB[1], 0ull);
        a0 = fma2(xv1.x, KA[2], a0);  b0 = fma2(xv1.x, KB[2], b0);
        a1 = fma2(xv1.y, KA[3], a1);  b1 = fma2(xv1.y, KB[3], b1);
        a0 = fma2(xv2.x, KA[4], a0);  b0 = fma2(xv2.x, KB[4], b0);
        a1 = fma2(xv2.y, KA[5], a1);  b1 = fma2(xv2.y, KB[5], b1);
        a0 = fma2(xv3.x, KA[6], a0);  b0 = fma2(xv3.x, KB[6], b0);
        a1 = fma2(xv3.y, KA[7], a1);  b1 = fma2(xv3.y, KB[7], b1);
        float lo, hi;
        unpack2(add2(a0, a1), lo, hi); const float v0 = bf0 + (lo + hi);
        unpack2(add2(b0, b1), lo, hi); const float v1 = bf1 + (lo + hi);
        dst2[(size_t)r * 96 + gp] = __floats2half2_rn(v0, v1);
    }
}

// ---------------- Kernel 2: GRU scan — R8 structure verbatim (proven 412 us) ----------------
// One 64-thread CTA per batch; thread = column triple (z,r,h); in-thread gates via
// MUFU.TANH; one __syncthreads per step; occupancy 4 CTAs/SM -> 4 desynced domains
// feeding SMSP0/1 with 4 warps each.
__global__ __launch_bounds__(HH, 4)
void gru_scan_kernel(const float* __restrict__ inputs,   // (B,S,16) - for delta mean
                     const float* __restrict__ r_in,     // (64,192)
                     const float* __restrict__ bias,     // (2,192)
                     const float* __restrict__ w1,       // (64,64)
                     const float* __restrict__ b1,       // (64)
                     const float* __restrict__ bn_gamma,
                     const float* __restrict__ bn_beta,
                     const float* __restrict__ bn_mean,
                     const float* __restrict__ bn_var,
                     const float* __restrict__ w2,       // (64,1)
                     const float* __restrict__ b2,       // (1)
                     const float* __restrict__ Tp,       // (1)
                     float* __restrict__ out)            // (B,1)
{
    __shared__ __align__(16) float sm_h[2][HH];   // double-buffered hidden state
    __shared__ float sm_e[HH];
    __shared__ float sm_r[HH];

    const int j = threadIdx.x;    // column triple 0..63
    const int b = blockIdx.x;     // batch

    // Recurrent weights for columns j (z), 64+j (r), 128+j (h); f32x2 pairs over k
    u64 Rz[32], Rr[32], Rh[32];
    #pragma unroll
    for (int k2 = 0; k2 < 32; k2++) {
        Rz[k2] = pack2(r_in[(2 * k2) * GG + j],        r_in[(2 * k2 + 1) * GG + j]);
        Rr[k2] = pack2(r_in[(2 * k2) * GG + 64 + j],   r_in[(2 * k2 + 1) * GG + 64 + j]);
        Rh[k2] = pack2(r_in[(2 * k2) * GG + 128 + j],  r_in[(2 * k2 + 1) * GG + 128 + j]);
    }
    const float brh = bias[GG + 128 + j];   // only h-gate recurrent bias remains

    sm_h[0][j] = 0.0f;

    const __half* xpp = g_xp + (size_t)b * SSP * GG;
    // prefetch x-projection for s=0,1 (biases folded at prepass)
    float xz0 = __half2float(xpp[j]);
    float xr0 = __half2float(xpp[64 + j]);
    float xh0 = __half2float(xpp[128 + j]);
    float xz1 = __half2float(xpp[GG + j]);
    float xr1 = __half2float(xpp[GG + 64 + j]);
    float xh1 = __half2float(xpp[GG + 128 + j]);
    __syncthreads();

    for (int s = 0; s < SS; s++) {
        const int p = s & 1;

        // prefetch s+2 (padded rows: no predicate needed; pad rows are zero)
        const __half* qp = xpp + (size_t)(s + 2) * GG;
        float xz2 = __half2float(qp[j]);
        float xr2 = __half2float(qp[64 + j]);
        float xh2 = __half2float(qp[128 + j]);

        // three recurrent dots, all in-thread (96 fma2, 6 chains of depth 16)
        const ulonglong2* h4 = (const ulonglong2*)sm_h[p];   // broadcast LDS.128
        u64 az0 = 0ull, az1 = 0ull, ar0 = 0ull, ar1 = 0ull, ah0 = 0ull, ah1 = 0ull;
        #pragma unroll
        for (int q2 = 0; q2 < 16; q2++) {
            ulonglong2 hv = h4[q2];
            az0 = fma2(hv.x, Rz[2 * q2],     az0);
            ar0 = fma2(hv.x, Rr[2 * q2],     ar0);
            ah0 = fma2(hv.x, Rh[2 * q2],     ah0);
            az1 = fma2(hv.y, Rz[2 * q2 + 1], az1);
            ar1 = fma2(hv.y, Rr[2 * q2 + 1], ar1);
            ah1 = fma2(hv.y, Rh[2 * q2 + 1], ah1);
        }
        float lo, hi;
        unpack2(add2(az0, az1), lo, hi);  const float az  = xz0 + (lo + hi);
        unpack2(add2(ar0, ar1), lo, hi);  const float ar_ = xr0 + (lo + hi);
        unpack2(add2(ah0, ah1), lo, hi);  const float rh_ = brh + (lo + hi);

        // gates via MUFU.TANH (sigmoid(x) = 0.5 + 0.5*tanh(x/2))
        const float z  = 0.5f + 0.5f * tanh_fast(0.5f * az);
        const float r  = 0.5f + 0.5f * tanh_fast(0.5f * ar_);
        const float hh = tanh_fast(xh0 + r * rh_);
        const float ho = sm_h[p][j];
        sm_h[p ^ 1][j] = z * (ho - hh) + hh;

        xz0 = xz1; xr0 = xr1; xh0 = xh1;
        xz1 = xz2; xr1 = xr2; xh1 = xh2;
        __syncthreads();   // the ONLY barrier per step
    }

    // final h is in buffer 0 (SS even)
    const float* hf = sm_h[0];

    // ---------- delta mean (fused; once per batch) ----------
    {
        float s = 0.0f;
        const float* dp = inputs + ((size_t)b * SS + (size_t)j * 16) * FIN + 15;
        #pragma unroll
        for (int i = 0; i < 16; i++) s += dp[(size_t)i * FIN];
        sm_r[j] = s;
    }
    __syncthreads();
    if (j < 16) sm_r[j] += sm_r[j + 16] + sm_r[j + 32] + sm_r[j + 48];
    __syncthreads();
    if (j < 4)  sm_r[j] += sm_r[j + 4] + sm_r[j + 8] + sm_r[j + 12];
    __syncthreads();
    const float db = Tp[0] * ((sm_r[0] + sm_r[1]) + (sm_r[2] + sm_r[3])) * (1.0f / (float)SS);

    // ---------- Epilogue: MLP head + BN ----------
    {
        float acc = b1[j];
        #pragma unroll 8
        for (int k = 0; k < HH; k++)
            acc += (hf[k] + db) * w1[k * HH + j];
        float hr = fmaxf(acc, 0.0f);
        float hb = (hr - bn_mean[j]) * rsqrtf(bn_var[j] + 1e-3f) * bn_gamma[j] + bn_beta[j];
        sm_e[j] = hb * w2[j];
    }
    __syncthreads();

    if (j == 0) {
        float acc = b2[0];
        #pragma unroll 8
        for (int k = 0; k < HH; k++) acc += sm_e[k];
        out[b] = acc;
    }
}

extern "C" void kernel_launch(void* const* d_in, const int* in_sizes, int n_in,
                              void* d_out, int out_size) {
    const float* inputs   = (const float*)d_in[0];
    const float* gk       = (const float*)d_in[1];
    const float* grk      = (const float*)d_in[2];
    const float* gbias    = (const float*)d_in[3];
    const float* w1       = (const float*)d_in[4];
    const float* b1       = (const float*)d_in[5];
    const float* bn_gamma = (const float*)d_in[6];
    const float* bn_beta  = (const float*)d_in[7];
    const float* bn_mean  = (const float*)d_in[8];
    const float* bn_var   = (const float*)d_in[9];
    const float* w2       = (const float*)d_in[10];
    const float* b2       = (const float*)d_in[11];
    const float* T        = (const float*)d_in[12];
    float* out = (float*)d_out;

    xproj_kernel<<<(BB * SS) / XROWS, NTP>>>(inputs, gk, gbias);
    gru_scan_kernel<<<BB, HH>>>(inputs, grk, gbias, w1, b1,
                                bn_gamma, bn_beta, bn_mean, bn_var,
                                w2, b2, T, out);
}

// round 15
// speedup vs baseline: 1.6268x; 1.1200x over previous
#include <cuda_runtime.h>
#include <cuda_bf16.h>
#include <cuda_fp16.h>

// Problem constants
#define BB   512
#define SS   1024
#define SSP  (SS + 2)  // padded rows per batch (prefetch overrun; pad rows stay 0)
#define FIN  16        // features per (b,s); feature 15 is delta
#define HH   64
#define GG   192       // 3*H
#define XROWS 64       // rows per x-projection block
#define NTP  256       // xproj threads: 4 row-groups x 64 column-triples

typedef unsigned long long u64;

// Device scratch (sanctioned alternative to cudaMalloc).
// Quad layout: per (batch,row,j): 4 halves = (z_pre, r_pre, h_pre, 0) -> one 8B access.
__device__ uint2 g_xpq[(size_t)BB * SSP * HH];   // ~268 MB

// ---- packed f32x2 helpers (bit-exact fp32, 2 FMA per fma-pipe slot) ----
__device__ __forceinline__ u64 pack2(float lo, float hi) {
    u64 r; asm("mov.b64 %0, {%1, %2};" : "=l"(r) : "f"(lo), "f"(hi)); return r;
}
__device__ __forceinline__ void unpack2(u64 v, float& lo, float& hi) {
    asm("mov.b64 {%0, %1}, %2;" : "=f"(lo), "=f"(hi) : "l"(v));
}
__device__ __forceinline__ u64 fma2(u64 a, u64 b, u64 c) {
    u64 d; asm("fma.rn.f32x2 %0, %1, %2, %3;" : "=l"(d) : "l"(a), "l"(b), "l"(c)); return d;
}
__device__ __forceinline__ u64 add2(u64 a, u64 b) {
    u64 d; asm("add.rn.f32x2 %0, %1, %2;" : "=l"(d) : "l"(a), "l"(b)); return d;
}
__device__ __forceinline__ float tanh_fast(float x) {
    float t; asm("tanh.approx.f32 %0, %1;" : "=f"(t) : "f"(x)); return t;
}

// ---------------- Kernel 1: x-projection pre-pass (quad fp16 out, biases folded) ----------------
// Thread = (row-group rg, column triple j). Computes z,r,h pre-activations for its j
// and stores ONE coalesced 8B quad per row. z,r fold input+recurrent bias; h folds input bias.
__global__ __launch_bounds__(NTP)
void xproj_kernel(const float* __restrict__ inputs,
                  const float* __restrict__ k_in,
                  const float* __restrict__ bias) {
    __shared__ __align__(16) float sx[XROWS * FIN];    // 4 KB
    const int tid = threadIdx.x;
    const int rg  = tid >> 6;          // row group 0..3 (16 rows each)
    const int j   = tid & 63;          // column triple
    const int bb  = blockIdx.x / (SS / XROWS);
    const int s0  = (blockIdx.x % (SS / XROWS)) * XROWS;
    const size_t row0  = (size_t)bb * SS + s0;
    const size_t drow0 = (size_t)bb * SSP + s0;

    // K weights for columns j (z), 64+j (r), 128+j (h); f32x2 pairs over f (f=15 masked)
    u64 Kz[8], Kr[8], Kh[8];
    #pragma unroll
    for (int f2 = 0; f2 < 8; f2++) {
        const int f = 2 * f2;
        const bool hv = (f + 1 < 15);
        Kz[f2] = pack2(k_in[f * GG + j],        hv ? k_in[(f + 1) * GG + j]        : 0.0f);
        Kr[f2] = pack2(k_in[f * GG + 64 + j],   hv ? k_in[(f + 1) * GG + 64 + j]   : 0.0f);
        Kh[f2] = pack2(k_in[f * GG + 128 + j],  hv ? k_in[(f + 1) * GG + 128 + j]  : 0.0f);
    }
    const float bfz = bias[j]        + bias[GG + j];
    const float bfr = bias[64 + j]   + bias[GG + 64 + j];
    const float bfh = bias[128 + j];                       // h recurrent bias stays in scan

    const float4* src = (const float4*)(inputs + row0 * FIN);
    for (int i = tid; i < XROWS * 4; i += NTP) ((float4*)sx)[i] = src[i];
    __syncthreads();

    uint2* dst = g_xpq + drow0 * HH + j;
    #pragma unroll 4
    for (int rr = 0; rr < XROWS / 4; rr++) {
        const int r = rg * (XROWS / 4) + rr;
        const ulonglong2* xr = (const ulonglong2*)(sx + r * FIN);
        u64 az0 = 0ull, az1 = 0ull, ar0 = 0ull, ar1 = 0ull, ah0 = 0ull, ah1 = 0ull;
        #pragma unroll
        for (int q = 0; q < 4; q++) {
            ulonglong2 xv = xr[q];
            az0 = fma2(xv.x, Kz[2 * q],     az0);
            ar0 = fma2(xv.x, Kr[2 * q],     ar0);
            ah0 = fma2(xv.x, Kh[2 * q],     ah0);
            az1 = fma2(xv.y, Kz[2 * q + 1], az1);
            ar1 = fma2(xv.y, Kr[2 * q + 1], ar1);
            ah1 = fma2(xv.y, Kh[2 * q + 1], ah1);
        }
        float lo, hi;
        unpack2(add2(az0, az1), lo, hi);  const float vz = bfz + (lo + hi);
        unpack2(add2(ar0, ar1), lo, hi);  const float vr = bfr + (lo + hi);
        unpack2(add2(ah0, ah1), lo, hi);  const float vh = bfh + (lo + hi);
        __half2 qa = __floats2half2_rn(vz, vr);
        __half2 qb = __floats2half2_rn(vh, 0.0f);
        uint2 quad;
        quad.x = *(const unsigned int*)&qa;
        quad.y = *(const unsigned int*)&qb;
        dst[(size_t)r * HH] = quad;     // warp: 32 consecutive j -> 256B coalesced STG.64
    }
}

// ---------------- Kernel 2: GRU scan — R8 structure (proven ~408 us) + quad xp loads ----------------
// One 64-thread CTA per batch; thread = column triple; in-thread gates via MUFU.TANH;
// one __syncthreads per step; occ 4 -> 4 desynced CTAs feeding SMSP0/1 (fma-pipe-bound).
__global__ __launch_bounds__(HH, 4)
void gru_scan_kernel(const float* __restrict__ inputs,   // (B,S,16) - for delta mean
                     const float* __restrict__ r_in,     // (64,192)
                     const float* __restrict__ bias,     // (2,192)
                     const float* __restrict__ w1,       // (64,64)
                     const float* __restrict__ b1,       // (64)
                     const float* __restrict__ bn_gamma,
                     const float* __restrict__ bn_beta,
                     const float* __restrict__ bn_mean,
                     const float* __restrict__ bn_var,
                     const float* __restrict__ w2,       // (64,1)
                     const float* __restrict__ b2,       // (1)
                     const float* __restrict__ Tp,       // (1)
                     float* __restrict__ out)            // (B,1)
{
    __shared__ __align__(16) float sm_h[2][HH];   // double-buffered hidden state
    __shared__ float sm_e[HH];
    __shared__ float sm_r[HH];

    const int j = threadIdx.x;    // column triple 0..63
    const int b = blockIdx.x;     // batch

    // Recurrent weights for columns j (z), 64+j (r), 128+j (h); f32x2 pairs over k
    u64 Rz[32], Rr[32], Rh[32];
    #pragma unroll
    for (int k2 = 0; k2 < 32; k2++) {
        Rz[k2] = pack2(r_in[(2 * k2) * GG + j],        r_in[(2 * k2 + 1) * GG + j]);
        Rr[k2] = pack2(r_in[(2 * k2) * GG + 64 + j],   r_in[(2 * k2 + 1) * GG + 64 + j]);
        Rh[k2] = pack2(r_in[(2 * k2) * GG + 128 + j],  r_in[(2 * k2 + 1) * GG + 128 + j]);
    }
    const float brh = bias[GG + 128 + j];   // only h-gate recurrent bias remains

    sm_h[0][j] = 0.0f;

    const uint2* xq = g_xpq + (size_t)b * SSP * HH + j;
    // prefetch quads for s=0,1 (kept raw; converted at use)
    uint2 q0 = xq[0];
    uint2 q1 = xq[HH];
    __syncthreads();

    for (int s = 0; s < SS; s++) {
        const int p = s & 1;

        // prefetch s+2 (padded rows: no predicate needed; pad rows are zero)
        uint2 q2 = xq[(size_t)(s + 2) * HH];

        // convert current step's quad
        const __half2 ha = *(const __half2*)&q0.x;   // (z_pre, r_pre)
        const __half2 hb = *(const __half2*)&q0.y;   // (h_pre, 0)
        const float xz0 = __low2float(ha);
        const float xr0 = __high2float(ha);
        const float xh0 = __low2float(hb);

        // three recurrent dots, all in-thread (96 fma2, 6 chains of depth 16)
        const ulonglong2* h4 = (const ulonglong2*)sm_h[p];   // broadcast LDS.128
        u64 az0 = 0ull, az1 = 0ull, ar0 = 0ull, ar1 = 0ull, ah0 = 0ull, ah1 = 0ull;
        #pragma unroll
        for (int q2i = 0; q2i < 16; q2i++) {
            ulonglong2 hv = h4[q2i];
            az0 = fma2(hv.x, Rz[2 * q2i],     az0);
            ar0 = fma2(hv.x, Rr[2 * q2i],     ar0);
            ah0 = fma2(hv.x, Rh[2 * q2i],     ah0);
            az1 = fma2(hv.y, Rz[2 * q2i + 1], az1);
            ar1 = fma2(hv.y, Rr[2 * q2i + 1], ar1);
            ah1 = fma2(hv.y, Rh[2 * q2i + 1], ah1);
        }
        float lo, hi;
        unpack2(add2(az0, az1), lo, hi);  const float az  = xz0 + (lo + hi);
        unpack2(add2(ar0, ar1), lo, hi);  const float ar_ = xr0 + (lo + hi);
        unpack2(add2(ah0, ah1), lo, hi);  const float rh_ = brh + (lo + hi);

        // gates via MUFU.TANH (sigmoid(x) = 0.5 + 0.5*tanh(x/2))
        const float z  = 0.5f + 0.5f * tanh_fast(0.5f * az);
        const float r  = 0.5f + 0.5f * tanh_fast(0.5f * ar_);
        const float hh = tanh_fast(xh0 + r * rh_);
        const float ho = sm_h[p][j];
        sm_h[p ^ 1][j] = z * (ho - hh) + hh;

        q0 = q1;
        q1 = q2;
        __syncthreads();   // the ONLY barrier per step
    }

    // final h is in buffer 0 (SS even)
    const float* hf = sm_h[0];

    // ---------- delta mean (fused; once per batch) ----------
    {
        float s = 0.0f;
        const float* dp = inputs + ((size_t)b * SS + (size_t)j * 16) * FIN + 15;
        #pragma unroll
        for (int i = 0; i < 16; i++) s += dp[(size_t)i * FIN];
        sm_r[j] = s;
    }
    __syncthreads();
    if (j < 16) sm_r[j] += sm_r[j + 16] + sm_r[j + 32] + sm_r[j + 48];
    __syncthreads();
    if (j < 4)  sm_r[j] += sm_r[j + 4] + sm_r[j + 8] + sm_r[j + 12];
    __syncthreads();
    const float db = Tp[0] * ((sm_r[0] + sm_r[1]) + (sm_r[2] + sm_r[3])) * (1.0f / (float)SS);

    // ---------- Epilogue: MLP head + BN ----------
    {
        float acc = b1[j];
        #pragma unroll 8
        for (int k = 0; k < HH; k++)
            acc += (hf[k] + db) * w1[k * HH + j];
        float hr = fmaxf(acc, 0.0f);
        float hb = (hr - bn_mean[j]) * rsqrtf(bn_var[j] + 1e-3f) * bn_gamma[j] + bn_beta[j];
        sm_e[j] = hb * w2[j];
    }
    __syncthreads();

    if (j == 0) {
        float acc = b2[0];
        #pragma unroll 8
        for (int k = 0; k < HH; k++) acc += sm_e[k];
        out[b] = acc;
    }
}

extern "C" void kernel_launch(void* const* d_in, const int* in_sizes, int n_in,
                              void* d_out, int out_size) {
    const float* inputs   = (const float*)d_in[0];
    const float* gk       = (const float*)d_in[1];
    const float* grk      = (const float*)d_in[2];
    const float* gbias    = (const float*)d_in[3];
    const float* w1       = (const float*)d_in[4];
    const float* b1       = (const float*)d_in[5];
    const float* bn_gamma = (const float*)d_in[6];
    const float* bn_beta  = (const float*)d_in[7];
    const float* bn_mean  = (const float*)d_in[8];
    const float* bn_var   = (const float*)d_in[9];
    const float* w2       = (const float*)d_in[10];
    const float* b2       = (const float*)d_in[11];
    const float* T        = (const float*)d_in[12];
    float* out = (float*)d_out;

    xproj_kernel<<<(BB * SS) / XROWS, NTP>>>(inputs, gk, gbias);
    gru_scan_kernel<<<BB, HH>>>(inputs, grk, gbias, w1, b1,
                                bn_gamma, bn_beta, bn_mean, bn_var,
                                w2, b2, T, out);
}